// round 1
// baseline (speedup 1.0000x reference)
#include <cuda_runtime.h>
#include <math.h>

// Problem constants
#define B_    4
#define NTOK  1032
#define C_    1024
#define H_    16
#define HD    64
#define BH    64            // B_*H_
#define M_ALL 4128          // B_*NTOK
#define SCALE 0.125f        // HD^-0.5
#define W_SOFT 0.8f         // TAU*(1-LAMBDA)
#define W_RCS  1.2f         // TAU*LAMBDA

// Scratch (static device allocations are allowed)
__device__ float g_K[BH * NTOK * HD];          // 16.9 MB
__device__ float g_V[BH * NTOK * HD];          // 16.9 MB
__device__ float g_S[(size_t)BH * NTOK * NTOK]; // 272.6 MB
__device__ float g_O[M_ALL * C_];              // 16.9 MB (b,n,c layout)

// ---------------------------------------------------------------------------
// Kernel 1: K,V projection.  C[m, j] = x[m,:] . qkv_w[1024+j, :] + qkv_b[1024+j]
// m in [0,4128) over (b,n); j in [0,2048): j<1024 -> K, else V. Scatter to
// head-major scratch. 128x128 tile, K-step 8, 256 threads, 8x8 microtile.
// ---------------------------------------------------------------------------
__global__ __launch_bounds__(256) void kv_proj_kernel(
    const float* __restrict__ x, const float* __restrict__ qkv_w,
    const float* __restrict__ qkv_b)
{
    __shared__ float As[8][128];
    __shared__ float Bs[8][128];
    const int tid = threadIdx.x;
    const int m0 = blockIdx.y * 128;
    const int j0 = blockIdx.x * 128;
    const int lrow = tid >> 1;
    const int lhalf = (tid & 1) * 4;
    const int tx = tid & 15, ty = tid >> 4;
    const float* Wk = qkv_w + (size_t)C_ * C_;   // skip q rows

    float acc[8][8];
#pragma unroll
    for (int i = 0; i < 8; i++)
#pragma unroll
        for (int j = 0; j < 8; j++) acc[i][j] = 0.f;

    for (int k0 = 0; k0 < C_; k0 += 8) {
        int am = m0 + lrow;
        float4 av = make_float4(0.f, 0.f, 0.f, 0.f);
        if (am < M_ALL)
            av = *(const float4*)(x + (size_t)am * C_ + k0 + lhalf);
        As[lhalf + 0][lrow] = av.x; As[lhalf + 1][lrow] = av.y;
        As[lhalf + 2][lrow] = av.z; As[lhalf + 3][lrow] = av.w;

        float4 bv = *(const float4*)(Wk + (size_t)(j0 + lrow) * C_ + k0 + lhalf);
        Bs[lhalf + 0][lrow] = bv.x; Bs[lhalf + 1][lrow] = bv.y;
        Bs[lhalf + 2][lrow] = bv.z; Bs[lhalf + 3][lrow] = bv.w;
        __syncthreads();

#pragma unroll
        for (int kk = 0; kk < 8; kk++) {
            float4 a0 = *(const float4*)&As[kk][ty * 8];
            float4 a1 = *(const float4*)&As[kk][ty * 8 + 4];
            float4 b0 = *(const float4*)&Bs[kk][tx * 8];
            float4 b1 = *(const float4*)&Bs[kk][tx * 8 + 4];
            float ra[8] = {a0.x, a0.y, a0.z, a0.w, a1.x, a1.y, a1.z, a1.w};
            float rb[8] = {b0.x, b0.y, b0.z, b0.w, b1.x, b1.y, b1.z, b1.w};
#pragma unroll
            for (int i = 0; i < 8; i++)
#pragma unroll
                for (int j = 0; j < 8; j++)
                    acc[i][j] = fmaf(ra[i], rb[j], acc[i][j]);
        }
        __syncthreads();
    }

#pragma unroll
    for (int i = 0; i < 8; i++) {
        int m = m0 + ty * 8 + i;
        if (m >= M_ALL) continue;
        int b = m / NTOK, n = m % NTOK;
#pragma unroll
        for (int j = 0; j < 8; j++) {
            int jc = j0 + tx * 8 + j;
            float v = acc[i][j] + qkv_b[C_ + jc];
            if (jc < C_) {
                int h = jc >> 6, d = jc & 63;
                g_K[(((size_t)b * H_ + h) * NTOK + n) * HD + d] = v;
            } else {
                int j2 = jc - C_;
                int h = j2 >> 6, d = j2 & 63;
                g_V[(((size_t)b * H_ + h) * NTOK + n) * HD + d] = v;
            }
        }
    }
}

// ---------------------------------------------------------------------------
// Kernel 2a: S[bh, m, n] = SCALE * (K[bh,m,:] . K[bh,n,:]) + add[m,n]
// ---------------------------------------------------------------------------
__global__ __launch_bounds__(256) void s_kernel(const float* __restrict__ add)
{
    __shared__ float As[8][128];
    __shared__ float Bs[8][128];
    const int bh = blockIdx.z;
    const int tid = threadIdx.x;
    const int m0 = blockIdx.y * 128;
    const int n0 = blockIdx.x * 128;
    const int lrow = tid >> 1;
    const int lhalf = (tid & 1) * 4;
    const int tx = tid & 15, ty = tid >> 4;
    const float* Kp = g_K + (size_t)bh * NTOK * HD;

    float acc[8][8];
#pragma unroll
    for (int i = 0; i < 8; i++)
#pragma unroll
        for (int j = 0; j < 8; j++) acc[i][j] = 0.f;

    for (int k0 = 0; k0 < HD; k0 += 8) {
        int am = m0 + lrow;
        float4 av = make_float4(0.f, 0.f, 0.f, 0.f);
        if (am < NTOK) av = *(const float4*)(Kp + (size_t)am * HD + k0 + lhalf);
        As[lhalf + 0][lrow] = av.x; As[lhalf + 1][lrow] = av.y;
        As[lhalf + 2][lrow] = av.z; As[lhalf + 3][lrow] = av.w;

        int bm = n0 + lrow;
        float4 bv = make_float4(0.f, 0.f, 0.f, 0.f);
        if (bm < NTOK) bv = *(const float4*)(Kp + (size_t)bm * HD + k0 + lhalf);
        Bs[lhalf + 0][lrow] = bv.x; Bs[lhalf + 1][lrow] = bv.y;
        Bs[lhalf + 2][lrow] = bv.z; Bs[lhalf + 3][lrow] = bv.w;
        __syncthreads();

#pragma unroll
        for (int kk = 0; kk < 8; kk++) {
            float4 a0 = *(const float4*)&As[kk][ty * 8];
            float4 a1 = *(const float4*)&As[kk][ty * 8 + 4];
            float4 b0 = *(const float4*)&Bs[kk][tx * 8];
            float4 b1 = *(const float4*)&Bs[kk][tx * 8 + 4];
            float ra[8] = {a0.x, a0.y, a0.z, a0.w, a1.x, a1.y, a1.z, a1.w};
            float rb[8] = {b0.x, b0.y, b0.z, b0.w, b1.x, b1.y, b1.z, b1.w};
#pragma unroll
            for (int i = 0; i < 8; i++)
#pragma unroll
                for (int j = 0; j < 8; j++)
                    acc[i][j] = fmaf(ra[i], rb[j], acc[i][j]);
        }
        __syncthreads();
    }

    float* Sp = g_S + (size_t)bh * NTOK * NTOK;
#pragma unroll
    for (int i = 0; i < 8; i++) {
        int m = m0 + ty * 8 + i;
        if (m >= NTOK) continue;
#pragma unroll
        for (int j = 0; j < 8; j++) {
            int n = n0 + tx * 8 + j;
            if (n >= NTOK) continue;
            Sp[(size_t)m * NTOK + n] = SCALE * acc[i][j] + add[(size_t)m * NTOK + n];
        }
    }
}

// ---------------------------------------------------------------------------
// Kernel 2b: in-place row softmax over g_S (row length 1032). One block/row.
// ---------------------------------------------------------------------------
__global__ __launch_bounds__(256) void softmax_kernel()
{
    __shared__ float red[32];
    const size_t row = blockIdx.x;
    float* p = g_S + row * NTOK;
    const int tid = threadIdx.x;
    const int lane = tid & 31, wid = tid >> 5;

    float vals[5];
    float vmax = -INFINITY;
#pragma unroll
    for (int i = 0; i < 5; i++) {
        int idx = tid + i * 256;
        vals[i] = (idx < NTOK) ? p[idx] : -INFINITY;
        vmax = fmaxf(vmax, vals[i]);
    }
#pragma unroll
    for (int o = 16; o > 0; o >>= 1)
        vmax = fmaxf(vmax, __shfl_xor_sync(0xffffffffu, vmax, o));
    if (lane == 0) red[wid] = vmax;
    __syncthreads();
    if (tid < 32) {
        float v = (tid < 8) ? red[tid] : -INFINITY;
#pragma unroll
        for (int o = 4; o > 0; o >>= 1)
            v = fmaxf(v, __shfl_xor_sync(0xffffffffu, v, o));
        if (tid == 0) red[0] = v;
    }
    __syncthreads();
    const float M = red[0];
    __syncthreads();

    float ssum = 0.f;
#pragma unroll
    for (int i = 0; i < 5; i++) {
        int idx = tid + i * 256;
        if (idx < NTOK) {
            vals[i] = __expf(vals[i] - M);
            ssum += vals[i];
        }
    }
#pragma unroll
    for (int o = 16; o > 0; o >>= 1)
        ssum += __shfl_xor_sync(0xffffffffu, ssum, o);
    if (lane == 0) red[wid] = ssum;
    __syncthreads();
    if (tid < 32) {
        float v = (tid < 8) ? red[tid] : 0.f;
#pragma unroll
        for (int o = 4; o > 0; o >>= 1)
            v += __shfl_xor_sync(0xffffffffu, v, o);
        if (tid == 0) red[0] = v;
    }
    __syncthreads();
    const float inv = 1.f / red[0];

#pragma unroll
    for (int i = 0; i < 5; i++) {
        int idx = tid + i * 256;
        if (idx < NTOK) p[idx] = vals[i] * inv;
    }
}

// ---------------------------------------------------------------------------
// Kernel 2c: O[bh,m,d] = sum_k (0.8*P[bh,m,k] + 1.2*rcs[bh,m,k]) * V[bh,k,d]
// 128x64 tile, K-step 8, 256 threads, 8x4 microtile. Writes g_O in (b,n,c).
// ---------------------------------------------------------------------------
__global__ __launch_bounds__(256) void ov_kernel(const float* __restrict__ rcs)
{
    __shared__ float As[8][128];
    __shared__ float Bs[8][64];
    const int bh = blockIdx.z;
    const int b = bh >> 4, h = bh & 15;
    const int tid = threadIdx.x;
    const int m0 = blockIdx.x * 128;
    const int lrow = tid >> 1;
    const int lhalf = (tid & 1) * 4;
    const int tx = tid & 15, ty = tid >> 4;

    const float* Sp = g_S + (size_t)bh * NTOK * NTOK;
    const float* Rp = rcs + (size_t)bh * NTOK * NTOK;
    const float* Vp = g_V + (size_t)bh * NTOK * HD;

    float acc[8][4];
#pragma unroll
    for (int i = 0; i < 8; i++)
#pragma unroll
        for (int j = 0; j < 4; j++) acc[i][j] = 0.f;

    for (int k0 = 0; k0 < NTOK; k0 += 8) {
        int am = m0 + lrow;
        float4 sv = make_float4(0.f, 0.f, 0.f, 0.f);
        float4 rv = make_float4(0.f, 0.f, 0.f, 0.f);
        if (am < NTOK) {
            sv = *(const float4*)(Sp + (size_t)am * NTOK + k0 + lhalf);
            rv = *(const float4*)(Rp + (size_t)am * NTOK + k0 + lhalf);
        }
        As[lhalf + 0][lrow] = W_SOFT * sv.x + W_RCS * rv.x;
        As[lhalf + 1][lrow] = W_SOFT * sv.y + W_RCS * rv.y;
        As[lhalf + 2][lrow] = W_SOFT * sv.z + W_RCS * rv.z;
        As[lhalf + 3][lrow] = W_SOFT * sv.w + W_RCS * rv.w;

        // B: 8 rows x 64 cols of V
        {
            int kr = tid >> 5;          // 0..7
            int col = (tid & 31) * 2;   // 0..62
            float2 bv = *(const float2*)(Vp + (size_t)(k0 + kr) * HD + col);
            Bs[kr][col] = bv.x;
            Bs[kr][col + 1] = bv.y;
        }
        __syncthreads();

#pragma unroll
        for (int kk = 0; kk < 8; kk++) {
            float4 a0 = *(const float4*)&As[kk][ty * 8];
            float4 a1 = *(const float4*)&As[kk][ty * 8 + 4];
            float4 b0 = *(const float4*)&Bs[kk][tx * 4];
            float ra[8] = {a0.x, a0.y, a0.z, a0.w, a1.x, a1.y, a1.z, a1.w};
            float rb[4] = {b0.x, b0.y, b0.z, b0.w};
#pragma unroll
            for (int i = 0; i < 8; i++)
#pragma unroll
                for (int j = 0; j < 4; j++)
                    acc[i][j] = fmaf(ra[i], rb[j], acc[i][j]);
        }
        __syncthreads();
    }

#pragma unroll
    for (int i = 0; i < 8; i++) {
        int m = m0 + ty * 8 + i;
        if (m >= NTOK) continue;
        float* op = g_O + ((size_t)b * NTOK + m) * C_ + h * HD + tx * 4;
#pragma unroll
        for (int j = 0; j < 4; j++) op[j] = acc[i][j];
    }
}

// ---------------------------------------------------------------------------
// Kernel 3: out[m, j] = g_O[m,:] . proj_w[j,:] + proj_b[j]
// ---------------------------------------------------------------------------
__global__ __launch_bounds__(256) void proj_kernel(
    const float* __restrict__ proj_w, const float* __restrict__ proj_b,
    float* __restrict__ out)
{
    __shared__ float As[8][128];
    __shared__ float Bs[8][128];
    const int tid = threadIdx.x;
    const int m0 = blockIdx.y * 128;
    const int j0 = blockIdx.x * 128;
    const int lrow = tid >> 1;
    const int lhalf = (tid & 1) * 4;
    const int tx = tid & 15, ty = tid >> 4;

    float acc[8][8];
#pragma unroll
    for (int i = 0; i < 8; i++)
#pragma unroll
        for (int j = 0; j < 8; j++) acc[i][j] = 0.f;

    for (int k0 = 0; k0 < C_; k0 += 8) {
        int am = m0 + lrow;
        float4 av = make_float4(0.f, 0.f, 0.f, 0.f);
        if (am < M_ALL)
            av = *(const float4*)(g_O + (size_t)am * C_ + k0 + lhalf);
        As[lhalf + 0][lrow] = av.x; As[lhalf + 1][lrow] = av.y;
        As[lhalf + 2][lrow] = av.z; As[lhalf + 3][lrow] = av.w;

        float4 bv = *(const float4*)(proj_w + (size_t)(j0 + lrow) * C_ + k0 + lhalf);
        Bs[lhalf + 0][lrow] = bv.x; Bs[lhalf + 1][lrow] = bv.y;
        Bs[lhalf + 2][lrow] = bv.z; Bs[lhalf + 3][lrow] = bv.w;
        __syncthreads();

#pragma unroll
        for (int kk = 0; kk < 8; kk++) {
            float4 a0 = *(const float4*)&As[kk][ty * 8];
            float4 a1 = *(const float4*)&As[kk][ty * 8 + 4];
            float4 b0 = *(const float4*)&Bs[kk][tx * 8];
            float4 b1 = *(const float4*)&Bs[kk][tx * 8 + 4];
            float ra[8] = {a0.x, a0.y, a0.z, a0.w, a1.x, a1.y, a1.z, a1.w};
            float rb[8] = {b0.x, b0.y, b0.z, b0.w, b1.x, b1.y, b1.z, b1.w};
#pragma unroll
            for (int i = 0; i < 8; i++)
#pragma unroll
                for (int j = 0; j < 8; j++)
                    acc[i][j] = fmaf(ra[i], rb[j], acc[i][j]);
        }
        __syncthreads();
    }

#pragma unroll
    for (int i = 0; i < 8; i++) {
        int m = m0 + ty * 8 + i;
        if (m >= M_ALL) continue;
#pragma unroll
        for (int j = 0; j < 8; j++) {
            int jc = j0 + tx * 8 + j;
            out[(size_t)m * C_ + jc] = acc[i][j] + proj_b[jc];
        }
    }
}

// ---------------------------------------------------------------------------
extern "C" void kernel_launch(void* const* d_in, const int* in_sizes, int n_in,
                              void* d_out, int out_size)
{
    const float* x      = (const float*)d_in[0];
    const float* qkv_w  = (const float*)d_in[1];
    const float* qkv_b  = (const float*)d_in[2];
    const float* proj_w = (const float*)d_in[3];
    const float* proj_b = (const float*)d_in[4];
    const float* addn   = (const float*)d_in[5];
    const float* rcs    = (const float*)d_in[6];
    float* out = (float*)d_out;

    // 1) K,V projection: M=4128, Nout=2048
    kv_proj_kernel<<<dim3(16, 33), 256>>>(x, qkv_w, qkv_b);
    // 2a) S = scale*K.K^T + add  (per bh 1032x1032)
    s_kernel<<<dim3(9, 9, BH), 256>>>(addn);
    // 2b) row softmax
    softmax_kernel<<<BH * NTOK, 256>>>();
    // 2c) O = (0.8 P + 1.2 rcs) @ V
    ov_kernel<<<dim3(9, 1, BH), 256>>>(rcs);
    // 3) output projection
    proj_kernel<<<dim3(8, 33), 256>>>(proj_w, proj_b, out);
}

// round 2
// speedup vs baseline: 2.2803x; 2.2803x over previous
#include <cuda_runtime.h>
#include <math.h>

// Problem constants
#define B_    4
#define NTOK  1032
#define C_    1024
#define H_    16
#define HD    64
#define BH    64            // B_*H_
#define M_ALL 4128          // B_*NTOK
#define SCALE 0.125f        // HD^-0.5
#define W_SOFT 0.8f         // TAU*(1-LAMBDA)
#define W_RCS  1.2f         // TAU*LAMBDA

#define LDA 20              // BK(16) + 4 pad, in 4B words

// Scratch
__device__ float g_K [BH * NTOK * HD];            // [bh][tok][d]
__device__ float g_Vt[BH * HD * NTOK];            // [bh][d][tok]  (transposed V)
__device__ float g_S [(size_t)BH * NTOK * NTOK];  // exp(S) (unnormalized)
__device__ float g_O [(size_t)M_ALL * C_];        // [b*n][c]
__device__ float g_rowsum[BH * NTOK];

__device__ __forceinline__ unsigned f2tf(float f) {
    unsigned u; asm("cvt.rna.tf32.f32 %0, %1;" : "=r"(u) : "f"(f)); return u;
}
__device__ __forceinline__ void mma_tf32(float* c, unsigned a0, unsigned a1,
                                         unsigned a2, unsigned a3,
                                         unsigned b0, unsigned b1) {
    asm volatile(
        "mma.sync.aligned.m16n8k8.row.col.f32.tf32.tf32.f32 "
        "{%0,%1,%2,%3},{%4,%5,%6,%7},{%8,%9},{%0,%1,%2,%3};"
        : "+f"(c[0]), "+f"(c[1]), "+f"(c[2]), "+f"(c[3])
        : "r"(a0), "r"(a1), "r"(a2), "r"(a3), "r"(b0), "r"(b1));
}

// ---------------------------------------------------------------------------
__global__ void zero_rowsum_kernel() {
    int i = blockIdx.x * 256 + threadIdx.x;
    if (i < BH * NTOK) g_rowsum[i] = 0.f;
}

// ---------------------------------------------------------------------------
// Kernel 1: K,V projection (tf32 mma). C[m,j] = x[m,:].Wk[j,:] + b, j in [0,2048)
// BM=128 BN=128 BK=16, 8 warps as 2x4 (warp tile 64x32).
// ---------------------------------------------------------------------------
__global__ __launch_bounds__(256) void kv_proj_kernel(
    const float* __restrict__ x, const float* __restrict__ qkv_w,
    const float* __restrict__ qkv_b)
{
    __shared__ unsigned As[128 * LDA];
    __shared__ unsigned Bs[128 * LDA];
    const int tid = threadIdx.x;
    const int m0 = blockIdx.y * 128, j0 = blockIdx.x * 128;
    const int wid = tid >> 5, lane = tid & 31;
    const int g = lane >> 2, t = lane & 3;
    const int wm = (wid >> 2) * 64, wn = (wid & 3) * 32;
    const int lrow = tid >> 1, lcol = (tid & 1) * 8;
    const float* Wk = qkv_w + (size_t)C_ * C_;

    float acc[4][4][4];
#pragma unroll
    for (int a = 0; a < 4; a++)
#pragma unroll
        for (int b = 0; b < 4; b++)
#pragma unroll
            for (int c = 0; c < 4; c++) acc[a][b][c] = 0.f;

    for (int k0 = 0; k0 < C_; k0 += 16) {
        float4 v0, v1;
        if (m0 + lrow < M_ALL) {
            const float* p = x + (size_t)(m0 + lrow) * C_ + k0 + lcol;
            v0 = *(const float4*)p; v1 = *(const float4*)(p + 4);
        } else { v0 = make_float4(0,0,0,0); v1 = v0; }
        unsigned* a = As + lrow * LDA + lcol;
        a[0]=f2tf(v0.x); a[1]=f2tf(v0.y); a[2]=f2tf(v0.z); a[3]=f2tf(v0.w);
        a[4]=f2tf(v1.x); a[5]=f2tf(v1.y); a[6]=f2tf(v1.z); a[7]=f2tf(v1.w);

        const float* q = Wk + (size_t)(j0 + lrow) * C_ + k0 + lcol;
        v0 = *(const float4*)q; v1 = *(const float4*)(q + 4);
        unsigned* bsp = Bs + lrow * LDA + lcol;
        bsp[0]=f2tf(v0.x); bsp[1]=f2tf(v0.y); bsp[2]=f2tf(v0.z); bsp[3]=f2tf(v0.w);
        bsp[4]=f2tf(v1.x); bsp[5]=f2tf(v1.y); bsp[6]=f2tf(v1.z); bsp[7]=f2tf(v1.w);
        __syncthreads();

#pragma unroll
        for (int ks = 0; ks < 16; ks += 8) {
            unsigned af[4][4], bf[4][2];
#pragma unroll
            for (int mt = 0; mt < 4; mt++) {
                const unsigned* ap = As + (wm + mt*16 + g) * LDA + ks + t;
                af[mt][0]=ap[0]; af[mt][1]=ap[8*LDA]; af[mt][2]=ap[4]; af[mt][3]=ap[8*LDA+4];
            }
#pragma unroll
            for (int nt = 0; nt < 4; nt++) {
                const unsigned* bp = Bs + (wn + nt*8 + g) * LDA + ks + t;
                bf[nt][0]=bp[0]; bf[nt][1]=bp[4];
            }
#pragma unroll
            for (int mt = 0; mt < 4; mt++)
#pragma unroll
                for (int nt = 0; nt < 4; nt++)
                    mma_tf32(acc[mt][nt], af[mt][0],af[mt][1],af[mt][2],af[mt][3],
                             bf[nt][0], bf[nt][1]);
        }
        __syncthreads();
    }

#pragma unroll
    for (int mt = 0; mt < 4; mt++) {
#pragma unroll
        for (int h = 0; h < 2; h++) {
            int m = m0 + wm + mt*16 + g + h*8;
            if (m >= M_ALL) continue;
            int b = m / NTOK, n = m - b * NTOK;
#pragma unroll
            for (int nt = 0; nt < 4; nt++) {
                int j = j0 + wn + nt*8 + t*2;
#pragma unroll
                for (int c = 0; c < 2; c++) {
                    int jj = j + c;
                    float v = acc[mt][nt][h*2 + c] + qkv_b[C_ + jj];
                    if (jj < C_) {
                        int hh = jj >> 6, d = jj & 63;
                        g_K[(((size_t)b*H_ + hh)*NTOK + n)*HD + d] = v;
                    } else {
                        int j2 = jj - C_;
                        int hh = j2 >> 6, d = j2 & 63;
                        g_Vt[(((size_t)b*H_ + hh)*HD + d)*NTOK + n] = v;
                    }
                }
            }
        }
    }
}

// ---------------------------------------------------------------------------
// Kernel 2: S' = exp(SCALE*K.K^T + add); accumulate row sums via atomics.
// BM=BN=128, BK=16, K=64 (4 iters).
// ---------------------------------------------------------------------------
__global__ __launch_bounds__(256) void s_kernel(const float* __restrict__ add)
{
    __shared__ unsigned As[128 * LDA];
    __shared__ unsigned Bs[128 * LDA];
    const int bh = blockIdx.z;
    const int tid = threadIdx.x;
    const int m0 = blockIdx.y * 128, n0 = blockIdx.x * 128;
    const int wid = tid >> 5, lane = tid & 31;
    const int g = lane >> 2, t = lane & 3;
    const int wm = (wid >> 2) * 64, wn = (wid & 3) * 32;
    const int lrow = tid >> 1, lcol = (tid & 1) * 8;
    const float* Kp = g_K + (size_t)bh * NTOK * HD;

    float acc[4][4][4];
#pragma unroll
    for (int a = 0; a < 4; a++)
#pragma unroll
        for (int b = 0; b < 4; b++)
#pragma unroll
            for (int c = 0; c < 4; c++) acc[a][b][c] = 0.f;

    for (int k0 = 0; k0 < HD; k0 += 16) {
        float4 v0, v1;
        if (m0 + lrow < NTOK) {
            const float* p = Kp + (size_t)(m0 + lrow) * HD + k0 + lcol;
            v0 = *(const float4*)p; v1 = *(const float4*)(p + 4);
        } else { v0 = make_float4(0,0,0,0); v1 = v0; }
        unsigned* a = As + lrow * LDA + lcol;
        a[0]=f2tf(v0.x); a[1]=f2tf(v0.y); a[2]=f2tf(v0.z); a[3]=f2tf(v0.w);
        a[4]=f2tf(v1.x); a[5]=f2tf(v1.y); a[6]=f2tf(v1.z); a[7]=f2tf(v1.w);

        if (n0 + lrow < NTOK) {
            const float* p = Kp + (size_t)(n0 + lrow) * HD + k0 + lcol;
            v0 = *(const float4*)p; v1 = *(const float4*)(p + 4);
        } else { v0 = make_float4(0,0,0,0); v1 = v0; }
        unsigned* bsp = Bs + lrow * LDA + lcol;
        bsp[0]=f2tf(v0.x); bsp[1]=f2tf(v0.y); bsp[2]=f2tf(v0.z); bsp[3]=f2tf(v0.w);
        bsp[4]=f2tf(v1.x); bsp[5]=f2tf(v1.y); bsp[6]=f2tf(v1.z); bsp[7]=f2tf(v1.w);
        __syncthreads();

#pragma unroll
        for (int ks = 0; ks < 16; ks += 8) {
            unsigned af[4][4], bf[4][2];
#pragma unroll
            for (int mt = 0; mt < 4; mt++) {
                const unsigned* ap = As + (wm + mt*16 + g) * LDA + ks + t;
                af[mt][0]=ap[0]; af[mt][1]=ap[8*LDA]; af[mt][2]=ap[4]; af[mt][3]=ap[8*LDA+4];
            }
#pragma unroll
            for (int nt = 0; nt < 4; nt++) {
                const unsigned* bp = Bs + (wn + nt*8 + g) * LDA + ks + t;
                bf[nt][0]=bp[0]; bf[nt][1]=bp[4];
            }
#pragma unroll
            for (int mt = 0; mt < 4; mt++)
#pragma unroll
                for (int nt = 0; nt < 4; nt++)
                    mma_tf32(acc[mt][nt], af[mt][0],af[mt][1],af[mt][2],af[mt][3],
                             bf[nt][0], bf[nt][1]);
        }
        __syncthreads();
    }

    float* Sp = g_S + (size_t)bh * NTOK * NTOK;
    float* rsp = g_rowsum + bh * NTOK;
#pragma unroll
    for (int mt = 0; mt < 4; mt++) {
#pragma unroll
        for (int h = 0; h < 2; h++) {
            int m = m0 + wm + mt*16 + g + h*8;
            float rp = 0.f;
            if (m < NTOK) {
#pragma unroll
                for (int nt = 0; nt < 4; nt++) {
                    int n = n0 + wn + nt*8 + t*2;
                    float e0 = 0.f, e1 = 0.f;
                    if (n < NTOK) {
                        e0 = __expf(SCALE * acc[mt][nt][h*2+0] + add[(size_t)m*NTOK + n]);
                        Sp[(size_t)m*NTOK + n] = e0;
                    }
                    if (n + 1 < NTOK) {
                        e1 = __expf(SCALE * acc[mt][nt][h*2+1] + add[(size_t)m*NTOK + n + 1]);
                        Sp[(size_t)m*NTOK + n + 1] = e1;
                    }
                    rp += e0 + e1;
                }
            }
            rp += __shfl_xor_sync(0xffffffffu, rp, 1);
            rp += __shfl_xor_sync(0xffffffffu, rp, 2);
            if (t == 0 && m < NTOK) atomicAdd(&rsp[m], rp);
        }
    }
}

// ---------------------------------------------------------------------------
// Kernel 3: O = (0.8*S'/rowsum + 1.2*rcs) @ V   (tf32 mma)
// BM=128 BN=64 BK=16, 8 warps as 4x2 (warp tile 32x32). K=1032 (65 iters).
// ---------------------------------------------------------------------------
__global__ __launch_bounds__(256) void ov_kernel(const float* __restrict__ rcs)
{
    __shared__ unsigned As[128 * LDA];
    __shared__ unsigned Bs[64 * LDA];
    const int bh = blockIdx.z;
    const int b = bh >> 4, hh = bh & 15;
    const int tid = threadIdx.x;
    const int m0 = blockIdx.x * 128;
    const int wid = tid >> 5, lane = tid & 31;
    const int g = lane >> 2, t = lane & 3;
    const int wm = (wid >> 1) * 32, wn = (wid & 1) * 32;
    const int lrow = tid >> 1, lcol = (tid & 1) * 8;
    const int brow = tid >> 2, bcol = (tid & 3) * 4;

    const float* Sp = g_S + (size_t)bh * NTOK * NTOK;
    const float* Rp = rcs + (size_t)bh * NTOK * NTOK;
    const float* Vp = g_Vt + (size_t)bh * HD * NTOK;

    const int am = m0 + lrow;
    float invr = 0.f;
    if (am < NTOK) invr = W_SOFT / g_rowsum[bh * NTOK + am];
    const float* Sr = Sp + (size_t)am * NTOK;
    const float* Rr = Rp + (size_t)am * NTOK;
    const float* Vr = Vp + (size_t)brow * NTOK;

    float acc[2][4][4];
#pragma unroll
    for (int a = 0; a < 2; a++)
#pragma unroll
        for (int bb = 0; bb < 4; bb++)
#pragma unroll
            for (int c = 0; c < 4; c++) acc[a][bb][c] = 0.f;

    for (int k0 = 0; k0 < NTOK; k0 += 16) {
        unsigned* a = As + lrow * LDA + lcol;
        if (am < NTOK) {
#pragma unroll
            for (int half = 0; half < 2; half++) {
                int kk = k0 + lcol + half * 4;
                if (kk + 4 <= NTOK) {
                    float4 sv = *(const float4*)(Sr + kk);
                    float4 rv = *(const float4*)(Rr + kk);
                    a[half*4+0] = f2tf(invr*sv.x + W_RCS*rv.x);
                    a[half*4+1] = f2tf(invr*sv.y + W_RCS*rv.y);
                    a[half*4+2] = f2tf(invr*sv.z + W_RCS*rv.z);
                    a[half*4+3] = f2tf(invr*sv.w + W_RCS*rv.w);
                } else {
                    a[half*4+0]=0u; a[half*4+1]=0u; a[half*4+2]=0u; a[half*4+3]=0u;
                }
            }
        } else {
#pragma unroll
            for (int i = 0; i < 8; i++) a[i] = 0u;
        }

        unsigned* bsp = Bs + brow * LDA + bcol;
        {
            int kk = k0 + bcol;
            if (kk + 4 <= NTOK) {
                float4 bv = *(const float4*)(Vr + kk);
                bsp[0]=f2tf(bv.x); bsp[1]=f2tf(bv.y); bsp[2]=f2tf(bv.z); bsp[3]=f2tf(bv.w);
            } else {
                bsp[0]=0u; bsp[1]=0u; bsp[2]=0u; bsp[3]=0u;
            }
        }
        __syncthreads();

#pragma unroll
        for (int ks = 0; ks < 16; ks += 8) {
            unsigned af[2][4], bf[4][2];
#pragma unroll
            for (int mt = 0; mt < 2; mt++) {
                const unsigned* ap = As + (wm + mt*16 + g) * LDA + ks + t;
                af[mt][0]=ap[0]; af[mt][1]=ap[8*LDA]; af[mt][2]=ap[4]; af[mt][3]=ap[8*LDA+4];
            }
#pragma unroll
            for (int nt = 0; nt < 4; nt++) {
                const unsigned* bp = Bs + (wn + nt*8 + g) * LDA + ks + t;
                bf[nt][0]=bp[0]; bf[nt][1]=bp[4];
            }
#pragma unroll
            for (int mt = 0; mt < 2; mt++)
#pragma unroll
                for (int nt = 0; nt < 4; nt++)
                    mma_tf32(acc[mt][nt], af[mt][0],af[mt][1],af[mt][2],af[mt][3],
                             bf[nt][0], bf[nt][1]);
        }
        __syncthreads();
    }

#pragma unroll
    for (int mt = 0; mt < 2; mt++) {
#pragma unroll
        for (int h = 0; h < 2; h++) {
            int m = m0 + wm + mt*16 + g + h*8;
            if (m >= NTOK) continue;
            float* op = g_O + ((size_t)b * NTOK + m) * C_ + hh * HD;
#pragma unroll
            for (int nt = 0; nt < 4; nt++) {
                int d = wn + nt*8 + t*2;
                float2 v = make_float2(acc[mt][nt][h*2+0], acc[mt][nt][h*2+1]);
                *(float2*)(op + d) = v;
            }
        }
    }
}

// ---------------------------------------------------------------------------
// Kernel 4: out = g_O @ proj_w^T + proj_b   (tf32 mma), BM=128 BN=128 BK=16.
// ---------------------------------------------------------------------------
__global__ __launch_bounds__(256) void proj_kernel(
    const float* __restrict__ proj_w, const float* __restrict__ proj_b,
    float* __restrict__ out)
{
    __shared__ unsigned As[128 * LDA];
    __shared__ unsigned Bs[128 * LDA];
    const int tid = threadIdx.x;
    const int m0 = blockIdx.y * 128, j0 = blockIdx.x * 128;
    const int wid = tid >> 5, lane = tid & 31;
    const int g = lane >> 2, t = lane & 3;
    const int wm = (wid >> 2) * 64, wn = (wid & 3) * 32;
    const int lrow = tid >> 1, lcol = (tid & 1) * 8;

    float acc[4][4][4];
#pragma unroll
    for (int a = 0; a < 4; a++)
#pragma unroll
        for (int b = 0; b < 4; b++)
#pragma unroll
            for (int c = 0; c < 4; c++) acc[a][b][c] = 0.f;

    for (int k0 = 0; k0 < C_; k0 += 16) {
        float4 v0, v1;
        if (m0 + lrow < M_ALL) {
            const float* p = g_O + (size_t)(m0 + lrow) * C_ + k0 + lcol;
            v0 = *(const float4*)p; v1 = *(const float4*)(p + 4);
        } else { v0 = make_float4(0,0,0,0); v1 = v0; }
        unsigned* a = As + lrow * LDA + lcol;
        a[0]=f2tf(v0.x); a[1]=f2tf(v0.y); a[2]=f2tf(v0.z); a[3]=f2tf(v0.w);
        a[4]=f2tf(v1.x); a[5]=f2tf(v1.y); a[6]=f2tf(v1.z); a[7]=f2tf(v1.w);

        const float* q = proj_w + (size_t)(j0 + lrow) * C_ + k0 + lcol;
        v0 = *(const float4*)q; v1 = *(const float4*)(q + 4);
        unsigned* bsp = Bs + lrow * LDA + lcol;
        bsp[0]=f2tf(v0.x); bsp[1]=f2tf(v0.y); bsp[2]=f2tf(v0.z); bsp[3]=f2tf(v0.w);
        bsp[4]=f2tf(v1.x); bsp[5]=f2tf(v1.y); bsp[6]=f2tf(v1.z); bsp[7]=f2tf(v1.w);
        __syncthreads();

#pragma unroll
        for (int ks = 0; ks < 16; ks += 8) {
            unsigned af[4][4], bf[4][2];
#pragma unroll
            for (int mt = 0; mt < 4; mt++) {
                const unsigned* ap = As + (wm + mt*16 + g) * LDA + ks + t;
                af[mt][0]=ap[0]; af[mt][1]=ap[8*LDA]; af[mt][2]=ap[4]; af[mt][3]=ap[8*LDA+4];
            }
#pragma unroll
            for (int nt = 0; nt < 4; nt++) {
                const unsigned* bp = Bs + (wn + nt*8 + g) * LDA + ks + t;
                bf[nt][0]=bp[0]; bf[nt][1]=bp[4];
            }
#pragma unroll
            for (int mt = 0; mt < 4; mt++)
#pragma unroll
                for (int nt = 0; nt < 4; nt++)
                    mma_tf32(acc[mt][nt], af[mt][0],af[mt][1],af[mt][2],af[mt][3],
                             bf[nt][0], bf[nt][1]);
        }
        __syncthreads();
    }

#pragma unroll
    for (int mt = 0; mt < 4; mt++) {
#pragma unroll
        for (int h = 0; h < 2; h++) {
            int m = m0 + wm + mt*16 + g + h*8;
            if (m >= M_ALL) continue;
#pragma unroll
            for (int nt = 0; nt < 4; nt++) {
                int j = j0 + wn + nt*8 + t*2;
                float2 v = make_float2(acc[mt][nt][h*2+0] + proj_b[j],
                                       acc[mt][nt][h*2+1] + proj_b[j+1]);
                *(float2*)(out + (size_t)m * C_ + j) = v;
            }
        }
    }
}

// ---------------------------------------------------------------------------
extern "C" void kernel_launch(void* const* d_in, const int* in_sizes, int n_in,
                              void* d_out, int out_size)
{
    const float* x      = (const float*)d_in[0];
    const float* qkv_w  = (const float*)d_in[1];
    const float* qkv_b  = (const float*)d_in[2];
    const float* proj_w = (const float*)d_in[3];
    const float* proj_b = (const float*)d_in[4];
    const float* addn   = (const float*)d_in[5];
    const float* rcs    = (const float*)d_in[6];
    float* out = (float*)d_out;

    zero_rowsum_kernel<<<(BH * NTOK + 255) / 256, 256>>>();
    kv_proj_kernel<<<dim3(16, 33), 256>>>(x, qkv_w, qkv_b);
    s_kernel<<<dim3(9, 9, BH), 256>>>(addn);
    ov_kernel<<<dim3(9, 1, BH), 256>>>(rcs);
    proj_kernel<<<dim3(8, 33), 256>>>(proj_w, proj_b, out);
}